// round 9
// baseline (speedup 1.0000x reference)
#include <cuda_runtime.h>
#include <math.h>
#include <stdint.h>

#define N_TOK 16384
#define DIM   2048
#define NEXP  64
#define KSEL  9
#define EPS_C 0.01f
#define INV_SIG_SQRT2 45.254833995939045f

#define BM 112
#define GRID 147                   // ceil(16384/112)
#define NTHR 512
#define BK 32
#define NCHUNK (DIM / BK)          // 64
#define NSTAGE 4
#define XTS 36                     // x smem row stride (u32)
#define XTILE (BM * XTS)           // 4032 u32
#define WTILE (BK * 128)           // 4096 u32
#define STAGEU (XTILE + WTILE)     // 8128 u32 = 32512 B
#define SMEM_BYTES (NSTAGE * STAGEU * 4)   // 130048 B
#define XV4 (BM * 8)               // 896 float4 per x stage
#define WV4 (WTILE / 4)            // 1024 float4 per W stage

// logits scratch: [row][128] (0-63 raw dot, 64-127 noise-pre dot) = 8 MB
__device__ __align__(16) float g_lg[(size_t)N_TOK * 128];

__device__ __forceinline__ unsigned long long pack_dup(float a) {
    unsigned long long r;
    unsigned ai = __float_as_uint(a);
    asm("mov.b64 %0, {%1, %1};" : "=l"(r) : "r"(ai));
    return r;
}
__device__ __forceinline__ uint32_t smem_u32(const void* p) {
    uint32_t a;
    asm("{ .reg .u64 t; cvta.to.shared.u64 t, %1; cvt.u32.u64 %0, t; }"
        : "=r"(a) : "l"(p));
    return a;
}
__device__ __forceinline__ void cp16(uint32_t dst, const void* src) {
    asm volatile("cp.async.ca.shared.global [%0], [%1], 16;"
                 :: "r"(dst), "l"(src) : "memory");
}

// ---------------- GEMM: fp32 FFMA2, 112x128 per CTA, 512 thr, 147 CTAs ----------------
extern "C" __global__ void __launch_bounds__(NTHR, 1)
gemm_kernel(const float* __restrict__ x, const float* __restrict__ Wr,
            const float* __restrict__ Wn)
{
    extern __shared__ uint32_t smu[];
    const uint32_t sbase = smem_u32(smu);
    const int tid  = threadIdx.x;
    const int trow = tid >> 5;       // 0..15 -> rows 7*trow..7*trow+6
    const int lane = tid & 31;       // cols 4*lane..4*lane+3
    const int row0 = blockIdx.x * BM;

    // ---- x cp.async map: 896 float4 over 512 threads x 2 iters (guarded) ----
    const float* xsrc[2];
    uint32_t     xoff[2];
    bool         xact[2];
    #pragma unroll
    for (int i = 0; i < 2; i++) {
        int idx = tid + NTHR * i;
        xact[i] = (idx < XV4);
        int r = xact[i] ? (idx >> 3) : 0, seg = xact[i] ? (idx & 7) : 0;
        int grow = row0 + r; if (grow > N_TOK - 1) grow = N_TOK - 1;  // tail clamp
        xsrc[i] = x + (size_t)grow * DIM + seg * 4;
        xoff[i] = (uint32_t)((r * XTS + seg * 4) * 4);
    }
    // ---- W cp.async map: 1024 float4 over 512 threads x 2 iters ----
    const float* wsrc[2];
    uint32_t     woff[2];
    #pragma unroll
    for (int i = 0; i < 2; i++) {
        int idx = tid + NTHR * i;               // 0..1023
        int kk = idx >> 5, q = idx & 31;
        int wcol = 4 * q;
        const float* base = (wcol < 64) ? (Wr + wcol) : (Wn + wcol - 64);
        wsrc[i] = base + (size_t)kk * NEXP;     // advance by c*BK rows each chunk
        woff[i] = (uint32_t)((XTILE + kk * 128 + wcol) * 4);
    }

    unsigned long long acc[7][2];
    #pragma unroll
    for (int i = 0; i < 7; i++) { acc[i][0] = 0ULL; acc[i][1] = 0ULL; }

    auto issue = [&](int c) {
        uint32_t buf = sbase + (uint32_t)((c & (NSTAGE - 1)) * STAGEU * 4);
        #pragma unroll
        for (int i = 0; i < 2; i++)
            if (xact[i]) cp16(buf + xoff[i], xsrc[i] + c * BK);
        #pragma unroll
        for (int i = 0; i < 2; i++)
            cp16(buf + woff[i], wsrc[i] + (size_t)c * BK * NEXP);
    };

    // prologue: stages 0..2
    #pragma unroll
    for (int p = 0; p < NSTAGE - 1; p++) {
        issue(p);
        asm volatile("cp.async.commit_group;" ::: "memory");
    }

    #pragma unroll 1
    for (int c = 0; c < NCHUNK; c++) {
        if (c < NCHUNK - 2)
            asm volatile("cp.async.wait_group 2;" ::: "memory");
        else if (c == NCHUNK - 2)
            asm volatile("cp.async.wait_group 1;" ::: "memory");
        else
            asm volatile("cp.async.wait_group 0;" ::: "memory");
        __syncthreads();
        if (c + NSTAGE - 1 < NCHUNK) {
            issue(c + NSTAGE - 1);              // stage (c-1)&3: readers passed barrier
            asm volatile("cp.async.commit_group;" ::: "memory");
        }

        const uint32_t* buf = smu + (c & (NSTAGE - 1)) * STAGEU;
        const float* xs = (const float*)buf;
        const float* ws = (const float*)(buf + XTILE);
        #pragma unroll 4
        for (int kk = 0; kk < BK; kk++) {
            ulonglong2 b2 = *(const ulonglong2*)(ws + kk * 128 + 4 * lane);
            unsigned long long a2[7];
            #pragma unroll
            for (int i = 0; i < 7; i++)
                a2[i] = pack_dup(xs[(7 * trow + i) * XTS + kk]);   // warp-uniform bcast
            #pragma unroll
            for (int i = 0; i < 7; i++) {
                asm("fma.rn.f32x2 %0, %1, %2, %0;"
                    : "+l"(acc[i][0]) : "l"(a2[i]), "l"(b2.x));
                asm("fma.rn.f32x2 %0, %1, %2, %0;"
                    : "+l"(acc[i][1]) : "l"(a2[i]), "l"(b2.y));
            }
        }
        // no bottom sync: next iteration's wait+sync orders stage reuse
    }

    // ---- write logits: 7 STG.128, lane-consecutive -> fully coalesced ----
    #pragma unroll
    for (int i = 0; i < 7; i++) {
        int row = row0 + 7 * trow + i;
        if (row < N_TOK)
            *(ulonglong2*)(g_lg + (size_t)row * 128 + 4 * lane)
                = make_ulonglong2(acc[i][0], acc[i][1]);
    }
}

// ---------------- epilogue: warp per row, redux-based top-9 ----------------
__device__ __forceinline__ uint32_t redux_max(uint32_t v) {
    uint32_t r;
    asm("redux.sync.max.u32 %0, %1, 0xffffffff;" : "=r"(r) : "r"(v));
    return r;
}
__device__ __forceinline__ uint32_t ordkey(float f) {
    uint32_t u = __float_as_uint(f);
    return ((int)u < 0) ? ~u : (u | 0x80000000u);
}
__device__ __forceinline__ float ordinv(uint32_t k) {
    return __uint_as_float(((int)k < 0) ? (k ^ 0x80000000u) : ~k);
}
__device__ __forceinline__ float wsum(float v) {
    #pragma unroll
    for (int o = 16; o; o >>= 1) v += __shfl_xor_sync(0xffffffffu, v, o);
    return v;
}

extern "C" __global__ void __launch_bounds__(256)
epi_kernel(const float* __restrict__ br,  const float* __restrict__ bn,
           const float* __restrict__ neps, const float* __restrict__ gum,
           float* __restrict__ out)
{
    __shared__ float imp_s[64], load_s[64];
    const int tid = threadIdx.x;
    const int wid = tid >> 5;
    const int lane = tid & 31;
    if (tid < 64) { imp_s[tid] = 0.f; load_s[tid] = 0.f; }
    __syncthreads();

    const int e0 = lane, e1 = lane + 32;
    const float br0 = br[e0], br1 = br[e1];
    const float bn0 = bn[e0], bn1 = bn[e1];
    float impa0 = 0.f, impa1 = 0.f, lda0 = 0.f, lda1 = 0.f;

    const int wg = blockIdx.x * 8 + wid;        // 0..4095
    #pragma unroll 1
    for (int rr = 0; rr < 4; rr++) {
        const int row = wg * 4 + rr;
        const float* L = g_lg + (size_t)row * 128;
        float raw0 = L[e0] + br0,      raw1 = L[e1] + br1;
        float pre0 = L[64 + e0] + bn0, pre1 = L[64 + e1] + bn1;
        float sd0 = fmaxf(pre0, 0.f) + log1pf(expf(-fabsf(pre0))) + EPS_C;
        float sd1 = fmaxf(pre1, 0.f) + log1pf(expf(-fabsf(pre1))) + EPS_C;
        float nz0 = fmaf(neps[(size_t)row * NEXP + e0], sd0, raw0);
        float nz1 = fmaf(neps[(size_t)row * NEXP + e1], sd1, raw1);
        float g0 = gum[(size_t)row * NEXP + e0];
        float g1 = gum[(size_t)row * NEXP + e1];

        // ---- top-9 via redux.max on orderable keys (exact, tie -> lowest idx) ----
        uint32_t k0 = ordkey(nz0), k1 = ordkey(nz1);
        float h0 = 0.f, h1 = 0.f, thr = 0.f, m1 = 0.f;
        #pragma unroll 1
        for (int t = 0; t < KSEL; t++) {
            uint32_t M = redux_max(k0 > k1 ? k0 : k1);
            if (t == 0) m1 = ordinv(M);
            thr = ordinv(M);
            unsigned b0 = __ballot_sync(0xffffffffu, k0 == M);
            unsigned b1 = __ballot_sync(0xffffffffu, k1 == M);
            if (b0) {
                if (lane == __ffs(b0) - 1) { h0 = 1.f; k0 = 0u; }
            } else {
                if (lane == __ffs(b1) - 1) { h1 = 1.f; k1 = 0u; }
            }
        }

        // ---- softmax maxes via redux, sums via shfl ----
        float m2 = ordinv(redux_max(ordkey(fmaxf(nz0 + g0, nz1 + g1))));
        float m3 = ordinv(redux_max(ordkey(fmaxf(raw0, raw1))));
        float E10 = expf(nz0 - m1),      E11 = expf(nz1 - m1);
        float E20 = expf(nz0 + g0 - m2), E21 = expf(nz1 + g1 - m2);
        float E30 = expf(raw0 - m3),     E31 = expf(raw1 - m3);
        float i1 = 1.f / wsum(E10 + E11);
        float i2 = 1.f / wsum(E20 + E21);
        float i3 = 1.f / wsum(E30 + E31);

        float ms0 = E20 * i2, ms1 = E21 * i2;
        float* om  = out + (size_t)row * NEXP;
        float* orp = out + (size_t)N_TOK * NEXP + (size_t)row * NEXP;
        om[e0]  = (h0 - ms0) + ms0;
        om[e1]  = (h1 - ms1) + ms1;
        orp[e0] = E10 * i1;
        orp[e1] = E11 * i1;

        impa0 += E30 * i3;
        impa1 += E31 * i3;
        float z0 = (thr - raw0) / sd0, z1 = (thr - raw1) / sd1;
        lda0 += 0.5f * (1.f - erff(z0 * INV_SIG_SQRT2));
        lda1 += 0.5f * (1.f - erff(z1 * INV_SIG_SQRT2));
    }

    atomicAdd(&imp_s[e0], impa0);
    atomicAdd(&imp_s[e1], impa1);
    atomicAdd(&load_s[e0], lda0);
    atomicAdd(&load_s[e1], lda1);
    __syncthreads();
    if (tid < 64) {
        atomicAdd(out + 2 * (size_t)N_TOK * NEXP + tid,        imp_s[tid]);
        atomicAdd(out + 2 * (size_t)N_TOK * NEXP + NEXP + tid, load_s[tid]);
    }
}

extern "C" void kernel_launch(void* const* d_in, const int* in_sizes, int n_in,
                              void* d_out, int out_size)
{
    const float* x    = (const float*)d_in[0];
    const float* Wr   = (const float*)d_in[1];
    const float* br   = (const float*)d_in[2];
    const float* Wn   = (const float*)d_in[3];
    const float* bn   = (const float*)d_in[4];
    const float* neps = (const float*)d_in[5];
    const float* gum  = (const float*)d_in[6];
    float* out = (float*)d_out;

    cudaMemsetAsync(out + 2 * (size_t)N_TOK * NEXP, 0, 2 * NEXP * sizeof(float));

    cudaFuncSetAttribute(gemm_kernel,
                         cudaFuncAttributeMaxDynamicSharedMemorySize, SMEM_BYTES);
    gemm_kernel<<<GRID, NTHR, SMEM_BYTES>>>(x, Wr, Wn);

    epi_kernel<<<N_TOK / 32, 256>>>(br, bn, neps, gum, out);
}